// round 17
// baseline (speedup 1.0000x reference)
#include <cuda_runtime.h>
#include <cuda_bf16.h>
#include <cuda_fp16.h>
#include <math.h>
#include <cstdint>

// Problem constants (fixed by setup_inputs)
#define V_N   20000
#define VPAD  20096
#define D_K   256
#define NHEAD 4
#define O_DIM 128
#define KCAT  1024           // NHEAD * D_K; k = h*256 + d, k-pair index = h*128 + dpair
#define KNBR  16

// ---------------- scratch (no allocations allowed) ----------------
__device__ __half   g_xh[(size_t)VPAD * D_K];          // x fp16 [v][d], 10.3 MB
__device__ float    g_attn[(size_t)V_N * NHEAD];       // attn [v][h]
__device__ float    g_wa[NHEAD * D_K];
__device__ float    g_bbar[O_DIM];
__device__ uint32_t g_WB[O_DIM * (KCAT / 2)];          // Wcat fp16 [n=o][k], 256 KB
__device__ int      g_adj64;

// ======================= helpers =======================
__device__ __forceinline__ uint32_t smem_u32(const void* p) {
    uint32_t a;
    asm("{ .reg .u64 t; cvta.to.shared.u64 t, %1; cvt.u32.u64 %0, t; }" : "=r"(a) : "l"(p));
    return a;
}
#define SW128(off) ((off) ^ (((off) >> 3) & 0x70))

#define LDSM4(r, addr) \
    asm volatile("ldmatrix.sync.aligned.m8n8.x4.shared.b16 {%0,%1,%2,%3}, [%4];" \
        : "=r"((r)[0]), "=r"((r)[1]), "=r"((r)[2]), "=r"((r)[3]) : "r"(addr))

#define MMAF16(c, a, b) \
    asm volatile("mma.sync.aligned.m16n8k16.row.col.f32.f16.f16.f32 " \
        "{%0,%1,%2,%3}, {%4,%5,%6,%7}, {%8,%9}, {%0,%1,%2,%3};" \
        : "+f"((c)[0]), "+f"((c)[1]), "+f"((c)[2]), "+f"((c)[3]) \
        : "r"((a)[0]), "r"((a)[1]), "r"((a)[2]), "r"((a)[3]), "r"((b)[0]), "r"((b)[1]))

#define CP_ASYNC16(dst, src) \
    asm volatile("cp.async.cg.shared.global [%0], [%1], 16;" :: "r"(dst), "l"(src))

// ---------------- merged prep: bprep (blk 0..127), wa (128..131), detect (132) ----------------
__global__ __launch_bounds__(256) void prep_misc_kernel(const float* __restrict__ W,
                                                        const float* __restrict__ a,
                                                        const float* __restrict__ b,
                                                        const void* __restrict__ adj) {
    int blk = blockIdx.x;
    int tid = threadIdx.x;
    if (blk < 128) {
        int o = blk;
        #pragma unroll
        for (int i = 0; i < 2; i++) {
            int q = tid + i * 256;          // k pair (2q, 2q+1), k = h*256 + d
            int k = 2 * q;
            int h = k >> 8, d = k & 255;
            float w0 = W[((size_t)h * D_K + d)     * O_DIM + o];
            float w1 = W[((size_t)h * D_K + d + 1) * O_DIM + o];
            __half2 p = __float22half2_rn(make_float2(w0, w1));
            g_WB[o * (KCAT / 2) + q] = *(uint32_t*)&p;
        }
    } else if (blk < 132) {
        int h = blk - 128;
        int d = tid;
        const float* Wd = W + ((size_t)h * D_K + d) * O_DIM;
        const float* ah = a + h * O_DIM;
        float s = 0.f;
        #pragma unroll 8
        for (int o = 0; o < O_DIM; o++) s += Wd[o] * ah[o];
        g_wa[h * D_K + d] = s;
        if (h == 0 && d < O_DIM)
            g_bbar[d] = 0.25f * (b[d] + b[O_DIM + d] + b[2 * O_DIM + d] + b[3 * O_DIM + d]);
    } else {
        __shared__ int s_bad;
        if (tid == 0) s_bad = 0;
        __syncthreads();
        if (tid < 64) {
            long long v = ((const long long*)adj)[tid];
            if (v < 0 || v > (long long)V_N) atomicOr(&s_bad, 1);
        }
        __syncthreads();
        if (tid == 0) g_adj64 = s_bad ? 0 : 1;
    }
}

// ---------------- x prep: fp16 convert + fused attn dots (wa in registers) ----------------
__global__ __launch_bounds__(256) void prepx_kernel(const float* __restrict__ x) {
    int tid  = threadIdx.x;
    int wid  = tid >> 5, lane = tid & 31;
    int d0   = lane * 8;

    float4 wra[NHEAD], wrb[NHEAD];
    #pragma unroll
    for (int h = 0; h < NHEAD; h++) {
        const float* wp = g_wa + h * D_K + d0;
        wra[h] = *(const float4*)wp;
        wrb[h] = *(const float4*)(wp + 4);
    }

    int vbase = blockIdx.x * 16 + wid * 2;
    #pragma unroll
    for (int r = 0; r < 2; r++) {
        int v = vbase + r;
        if (v >= V_N) continue;
        const float* xp = x + (size_t)v * D_K + d0;
        float4 va = *(const float4*)xp;
        float4 vb = *(const float4*)(xp + 4);

        __half2 p0 = __float22half2_rn(make_float2(va.x, va.y));
        __half2 p1 = __float22half2_rn(make_float2(va.z, va.w));
        __half2 p2 = __float22half2_rn(make_float2(vb.x, vb.y));
        __half2 p3 = __float22half2_rn(make_float2(vb.z, vb.w));
        ((uint4*)g_xh)[(size_t)v * 32 + lane] =
            make_uint4(*(uint32_t*)&p0, *(uint32_t*)&p1, *(uint32_t*)&p2, *(uint32_t*)&p3);

        float res[NHEAD];
        #pragma unroll
        for (int h = 0; h < NHEAD; h++) {
            float s = va.x * wra[h].x + va.y * wra[h].y + va.z * wra[h].z + va.w * wra[h].w
                    + vb.x * wrb[h].x + vb.y * wrb[h].y + vb.z * wrb[h].z + vb.w * wrb[h].w;
            #pragma unroll
            for (int off = 16; off; off >>= 1) s += __shfl_xor_sync(0xffffffffu, s, off);
            res[h] = s;
        }
        if (lane == 0)
            *(float4*)(g_attn + (size_t)v * NHEAD) =
                make_float4(res[0], res[1], res[2], res[3]);
    }
}

// ---------------- fused gather + GEMM ----------------
// CTA = 32 nodes. Phase 1: softmax coefs. Phase 2: full 32x1024 A-tile gather
// into smem (single phase). Phase 3: B-double-buffered MMA mainloop.
// smem: B 2x16KB @0, A 64KB @32768 (16 chunk-blocks of 4KB), coef @98304, idx @107008.
#define BM 32
#define NCHUNK 16
#define CSTRIDE 68
#define SOFF_A   32768
#define SOFF_CF  98304
#define SOFF_IX  107008
#define FSMEM_SZ 109568

__global__ __launch_bounds__(256) void fused_kernel(const void* __restrict__ adj,
                                                    float* __restrict__ out) {
    extern __shared__ char smem[];
    uint32_t sb  = smem_u32(smem);
    uint32_t sbA = sb + SOFF_A;
    float* sCoef = (float*)(smem + SOFF_CF);   // [row][k*4+h], stride CSTRIDE
    int*   sIdx  = (int*)(smem + SOFF_IX);     // [row][k]

    int tid  = threadIdx.x;
    int wid  = tid >> 5, lane = tid & 31;
    int m0   = blockIdx.x * BM;

    // ---- B prefetch chunks 0,1 (hidden under gather) ----
    #pragma unroll
    for (int st = 0; st < 2; st++) {
        #pragma unroll
        for (int i = 0; i < 4; i++) {
            int idx = tid + i * 256;
            int n = idx >> 3, seg = idx & 7;
            uint32_t sw = SW128((uint32_t)(n * 128 + seg * 16));
            CP_ASYNC16(sb + st * 16384 + sw, (const uint4*)g_WB + (size_t)n * 128 + st * 8 + seg);
        }
        asm volatile("cp.async.commit_group;" ::: "memory");
    }

    // ---- adjacency -> sIdx ----
    #pragma unroll
    for (int i = 0; i < 2; i++) {
        int id  = tid + i * 256;
        int row = id >> 4, k = id & 15;
        int v   = m0 + row;
        long long a;
        if (g_adj64) a = ((const long long*)adj)[(size_t)v * KNBR + k];
        else         a = (long long)((const int*)adj)[(size_t)v * KNBR + k];
        sIdx[row * KNBR + k] = (a >= 0 && a < (long long)V_N) ? (int)a : -1;
    }
    __syncthreads();

    // ---- softmax coefs: one thread per (row, head) ----
    if (tid < BM * NHEAD) {
        int row = tid >> 2, h = tid & 3;
        float sc[KNBR];
        #pragma unroll
        for (int k = 0; k < KNBR; k++) {
            int raw = sIdx[row * KNBR + k];
            sc[k] = (raw < 0) ? -1e9f : __ldg(g_attn + (size_t)raw * NHEAD + h);
        }
        float mx = -INFINITY;
        #pragma unroll
        for (int k = 0; k < KNBR; k++) mx = fmaxf(mx, sc[k]);
        float sum = 0.f;
        #pragma unroll
        for (int k = 0; k < KNBR; k++) { sc[k] = __expf(sc[k] - mx); sum += sc[k]; }
        float inv = 1.0f / sum;
        #pragma unroll
        for (int k = 0; k < KNBR; k++)
            sCoef[row * CSTRIDE + k * 4 + h] = (sIdx[row * KNBR + k] < 0) ? 0.f : sc[k] * inv;
    }
    __syncthreads();

    // ---- full gather: 2 rows per pass, thread owns (row, d-pair) ----
    const __half2* xh2 = (const __half2*)g_xh;
    int sub = tid >> 7;       // row within pair
    int dp  = tid & 127;      // d-pair 0..127
    #pragma unroll 4
    for (int iter = 0; iter < 16; iter++) {
        int row = iter * 2 + sub;
        const float* cf = sCoef + row * CSTRIDE;
        const int*   ix = sIdx  + row * KNBR;
        float2 acc[NHEAD];
        #pragma unroll
        for (int h = 0; h < NHEAD; h++) acc[h] = make_float2(0.f, 0.f);
        #pragma unroll
        for (int k = 0; k < KNBR; k++) {
            int n = ix[k];
            n = n < 0 ? 0 : n;
            float2 fv = __half22float2(__ldg(xh2 + (size_t)n * 128 + dp));
            float4 c4 = *(const float4*)(cf + k * 4);
            acc[0].x = fmaf(c4.x, fv.x, acc[0].x);  acc[0].y = fmaf(c4.x, fv.y, acc[0].y);
            acc[1].x = fmaf(c4.y, fv.x, acc[1].x);  acc[1].y = fmaf(c4.y, fv.y, acc[1].y);
            acc[2].x = fmaf(c4.z, fv.x, acc[2].x);  acc[2].y = fmaf(c4.z, fv.y, acc[2].y);
            acc[3].x = fmaf(c4.w, fv.x, acc[3].x);  acc[3].y = fmaf(c4.w, fv.y, acc[3].y);
        }
        #pragma unroll
        for (int h = 0; h < NHEAD; h++) {
            __half2 p = __float22half2_rn(make_float2(acc[h].x, acc[h].y));
            int kp = h * 128 + dp;                         // k-pair index
            uint32_t off = (uint32_t)(kp >> 5) * 4096u
                         + SW128((uint32_t)(row * 128 + (kp & 31) * 4));
            *(uint32_t*)(smem + SOFF_A + off) = *(uint32_t*)&p;
        }
    }
    __syncthreads();

    // ---- MMA mainloop: warp tile 32x16 (wn = wid*16) ----
    int wn  = wid * 16;
    int lrA = lane & 15;
    int hA  = lane >> 4;
    int lrB = (lane & 7) + ((lane >> 4) << 3);
    int hB  = (lane >> 3) & 1;

    float acc[2][2][4];
    #pragma unroll
    for (int i = 0; i < 2; i++)
        #pragma unroll
        for (int j = 0; j < 2; j++)
            #pragma unroll
            for (int q = 0; q < 4; q++) acc[i][j][q] = 0.f;

    for (int kc = 0; kc < NCHUNK; kc++) {
        if (kc + 2 < NCHUNK) {
            asm volatile("cp.async.wait_group 1;" ::: "memory");
        } else {
            asm volatile("cp.async.wait_group 0;" ::: "memory");
        }
        __syncthreads();

        uint32_t bbase = sb + (kc & 1) * 16384;
        uint32_t abase = sbA + kc * 4096;
        #pragma unroll
        for (int ks = 0; ks < 4; ks++) {
            uint32_t af[2][4];
            #pragma unroll
            for (int mt = 0; mt < 2; mt++) {
                uint32_t offA = SW128((uint32_t)((mt * 16 + lrA) * 128 + ks * 32 + hA * 16));
                LDSM4(af[mt], abase + offA);
            }
            uint32_t bf[4];
            uint32_t offB = SW128((uint32_t)((wn + lrB) * 128 + ks * 32 + hB * 16));
            LDSM4(bf, bbase + offB);
            #pragma unroll
            for (int mt = 0; mt < 2; mt++) {
                MMAF16(acc[mt][0], af[mt], &bf[0]);
                MMAF16(acc[mt][1], af[mt], &bf[2]);
            }
        }
        __syncthreads();

        if (kc + 2 < NCHUNK) {
            #pragma unroll
            for (int i = 0; i < 4; i++) {
                int idx = tid + i * 256;
                int n = idx >> 3, seg = idx & 7;
                uint32_t sw = SW128((uint32_t)(n * 128 + seg * 16));
                CP_ASYNC16(sb + (kc & 1) * 16384 + sw,
                           (const uint4*)g_WB + (size_t)n * 128 + (kc + 2) * 8 + seg);
            }
            asm volatile("cp.async.commit_group;" ::: "memory");
        }
    }

    // ---- epilogue: out = relu(0.25*acc + bbar); all rows valid (V_N % 32 == 0) ----
    int g  = lane >> 2;
    int t2 = (lane & 3) * 2;
    #pragma unroll
    for (int mt = 0; mt < 2; mt++) {
        int r0 = m0 + mt * 16 + g;
        #pragma unroll
        for (int nt = 0; nt < 2; nt++) {
            int c = wn + nt * 8 + t2;
            float bx = g_bbar[c], by = g_bbar[c + 1];
            float rx0 = fmaxf(fmaf(acc[mt][nt][0], 0.25f, bx), 0.f);
            float ry0 = fmaxf(fmaf(acc[mt][nt][1], 0.25f, by), 0.f);
            *(float2*)(out + (size_t)r0 * O_DIM + c) = make_float2(rx0, ry0);
            float rx1 = fmaxf(fmaf(acc[mt][nt][2], 0.25f, bx), 0.f);
            float ry1 = fmaxf(fmaf(acc[mt][nt][3], 0.25f, by), 0.f);
            *(float2*)(out + (size_t)(r0 + 8) * O_DIM + c) = make_float2(rx1, ry1);
        }
    }
}

// ---------------- launch ----------------
extern "C" void kernel_launch(void* const* d_in, const int* in_sizes, int n_in,
                              void* d_out, int out_size) {
    const float* x   = (const float*)d_in[0];   // [V, D]
    const float* W   = (const float*)d_in[1];   // [H, D, O]
    const float* a   = (const float*)d_in[2];   // [H, O]
    const float* b   = (const float*)d_in[3];   // [H, O]
    const void*  adj = d_in[4];                 // [V, K] int32 or int64
    float* out = (float*)d_out;                 // [V, O]

    cudaFuncSetAttribute(fused_kernel, cudaFuncAttributeMaxDynamicSharedMemorySize, FSMEM_SZ);

    prep_misc_kernel<<<133, 256>>>(W, a, b, adj);
    prepx_kernel<<<VPAD / 16, 256>>>(x);
    fused_kernel<<<V_N / BM, 256, FSMEM_SZ>>>(adj, out);   // 625 CTAs
}